// round 14
// baseline (speedup 1.0000x reference)
#include <cuda_runtime.h>
#include <cuda_fp16.h>
#include <cstdint>

// Problem constants
#define NCHUNK  256            // BATCH * NPEAK
#define CHLEN   512
#define HID     256
#define MDIM    283
#define KPADP   384            // proj K padded to 3*128
#define DEPTH   7
#define HLC     131072         // CHLEN * HID elements per chunk, [l][c] layout
#define NROWS   131072         // total l rows (NCHUNK * CHLEN)
#define BUF_ELEMS ((size_t)NCHUNK * HLC)

// Activation ping-pong buffers, split fp16 (hi + lo reconstructs fp32 to ~2^-22)
__device__ __half g_hiA[BUF_ELEMS];
__device__ __half g_loA[BUF_ELEMS];
__device__ __half g_hiB[BUF_ELEMS];
__device__ __half g_loB[BUF_ELEMS];

// Tower weights as single fp16 (11-bit mantissa): [layer][tap][o][i]
#define WPLANE 65536                               // 256*256 per (layer,tap)
__device__ __half g_w16[DEPTH * 3 * WPLANE];

// x split fp16 hi/lo + w_proj single fp16, K padded to 384
__device__ __half g_xHi[(size_t)NROWS * KPADP];
__device__ __half g_xLo[(size_t)NROWS * KPADP];
__device__ __half g_wp16[HID * KPADP];

__device__ __forceinline__ uint32_t smem_u32(const void* p) {
    uint32_t a;
    asm("{ .reg .u64 t; cvta.to.shared.u64 t, %1; cvt.u32.u64 %0, t; }" : "=r"(a) : "l"(p));
    return a;
}
__device__ __forceinline__ void split_f16(float v, __half& h, __half& l) {
    h = __float2half_rn(v);
    l = __float2half_rn(v - __half2float(h));
}
__device__ __forceinline__ void ldsm_x4(uint32_t* r, uint32_t addr) {
    asm volatile("ldmatrix.sync.aligned.m8n8.x4.shared.b16 {%0,%1,%2,%3}, [%4];"
        : "=r"(r[0]), "=r"(r[1]), "=r"(r[2]), "=r"(r[3]) : "r"(addr));
}
__device__ __forceinline__ void mma_16816(float* d, const uint32_t* a, const uint32_t* b) {
    asm volatile("mma.sync.aligned.m16n8k16.row.col.f32.f16.f16.f32 "
        "{%0,%1,%2,%3},{%4,%5,%6,%7},{%8,%9},{%0,%1,%2,%3};"
        : "+f"(d[0]), "+f"(d[1]), "+f"(d[2]), "+f"(d[3])
        : "r"(a[0]), "r"(a[1]), "r"(a[2]), "r"(a[3]), "r"(b[0]), "r"(b[1]));
}
__device__ __forceinline__ void cp16(uint32_t dst, const void* src, int srcsize) {
    asm volatile("cp.async.cg.shared.global [%0], [%1], 16, %2;"
                 :: "r"(dst), "l"(src), "r"(srcsize) : "memory");
}
__device__ __forceinline__ void cp_commit_wait() {
    asm volatile("cp.async.commit_group;" ::: "memory");
    asm volatile("cp.async.wait_group 0;" ::: "memory");
}

// ---------------------------------------------------------------------------
// Prep kernels
// ---------------------------------------------------------------------------
__global__ __launch_bounds__(256) void wprep_kernel(
    const float* __restrict__ w, __half* __restrict__ w16)
{
    size_t j = (size_t)blockIdx.x * 256 + threadIdx.x;     // < DEPTH*3*WPLANE
    int layer = (int)(j / (3 * WPLANE));
    int rem   = (int)(j % (3 * WPLANE));
    int t  = rem / WPLANE;
    int oi = rem % WPLANE;                                  // o*256 + i
    float v = w[(size_t)layer * 3 * WPLANE + (size_t)oi * 3 + t];
    w16[j] = __float2half_rn(v);
}

__global__ __launch_bounds__(256) void xsplit_kernel(
    const float* __restrict__ x, __half* __restrict__ xh, __half* __restrict__ xl)
{
    const size_t row = blockIdx.x;                          // < NROWS
    for (int m = threadIdx.x; m < KPADP; m += 256) {
        float v = (m < MDIM) ? x[row * MDIM + m] : 0.f;
        __half h, l;
        split_f16(v, h, l);
        xh[row * KPADP + m] = h;
        xl[row * KPADP + m] = l;
    }
}

__global__ __launch_bounds__(256) void wpsplit_kernel(
    const float* __restrict__ wp, __half* __restrict__ w16)
{
    const size_t c = blockIdx.x;                            // < HID
    for (int m = threadIdx.x; m < KPADP; m += 256) {
        float v = (m < MDIM) ? wp[c * MDIM + m] : 0.f;
        w16[c * KPADP + m] = __float2half_rn(v);
    }
}

// ---------------------------------------------------------------------------
// MMA tile geometry: fp16 2-pass, K=128 phases.
// CTA: 128 M x 128 N; 8 warps (2x4), warp tile 64x32.
// SMEM per phase: A(single) + B hi/lo, each 128 x 128 fp16 with LDA=136 pad
// (272B row stride, same 16B-step bank pattern as LDA=72 -> conflict-free).
// 3 * 34816 = 104448 B -> 2 CTAs/SM (209 KB < 228 KB).
// ---------------------------------------------------------------------------
#define LDA     136
#define ABUF    34816
#define SM_MMA  104448

// ---------------------------------------------------------------------------
// Projection via mma: D[c, row] = sum_m wp[c,m] x[row,m]; K=384, 3 phases.
// ---------------------------------------------------------------------------
__global__ __launch_bounds__(256, 2) void proj_mma_kernel(
    const __half* __restrict__ xh, const __half* __restrict__ xl,
    const __half* __restrict__ w16,
    __half* __restrict__ out_hi, __half* __restrict__ out_lo)
{
    extern __shared__ char smem[];
    const uint32_t sb = smem_u32(smem);
    const uint32_t sbA = sb, sbBh = sb + ABUF, sbBl = sb + 2 * ABUF;
    const int tid = threadIdx.x;
    const int wid = tid >> 5, lane = tid & 31;
    const int warp_m = wid >> 2, warp_n = wid & 3;
    const int rtile = blockIdx.x;        // row tile (128 rows)
    const int otile = blockIdx.y;        // c half

    float acc[4][4][4];
#pragma unroll
    for (int mi = 0; mi < 4; mi++)
#pragma unroll
        for (int ni = 0; ni < 4; ni++)
#pragma unroll
            for (int e = 0; e < 4; e++) acc[mi][ni][e] = 0.f;

    const int aRow = warp_m * 64 + (lane & 15);
    const int aCol = (lane >> 4) << 3;
    const int bRow = warp_n * 32 + ((lane & 7) | ((lane >> 4) << 3));
    const int bCol = ((lane >> 3) & 1) << 3;

#pragma unroll 1
    for (int k0 = 0; k0 < KPADP; k0 += 128) {
        __syncthreads();
        for (int idx = tid; idx < 2048; idx += 256) {
            const int r = idx >> 4, ch = idx & 15;
            const size_t gsrc = (size_t)(otile * 128 + r) * KPADP + k0 + ch * 8;
            const uint32_t sdst = (uint32_t)(r * LDA + ch * 8) * 2;
            cp16(sbA + sdst, w16 + gsrc, 16);
        }
        for (int idx = tid; idx < 2048; idx += 256) {
            const int r = idx >> 4, ch = idx & 15;
            const size_t gsrc = ((size_t)rtile * 128 + r) * KPADP + k0 + ch * 8;
            const uint32_t sdst = (uint32_t)(r * LDA + ch * 8) * 2;
            cp16(sbBh + sdst, xh + gsrc, 16);
            cp16(sbBl + sdst, xl + gsrc, 16);
        }
        cp_commit_wait();
        __syncthreads();
#pragma unroll
        for (int ks = 0; ks < 8; ks++) {
            uint32_t a4[4][4], bh[8], bl[8];
#pragma unroll
            for (int mi = 0; mi < 4; mi++) {
                const uint32_t off = (uint32_t)(((aRow + mi * 16) * LDA) + aCol + ks * 16) * 2;
                ldsm_x4(a4[mi], sbA + off);
            }
#pragma unroll
            for (int bi = 0; bi < 2; bi++) {
                const uint32_t off = (uint32_t)(((bRow + bi * 16) * LDA) + bCol + ks * 16) * 2;
                ldsm_x4(&bh[bi * 4], sbBh + off);
                ldsm_x4(&bl[bi * 4], sbBl + off);
            }
#pragma unroll
            for (int mi = 0; mi < 4; mi++)
#pragma unroll
                for (int ni = 0; ni < 4; ni++)
                    mma_16816(acc[mi][ni], a4[mi], &bh[ni * 2]);   // W * Hhi
#pragma unroll
            for (int mi = 0; mi < 4; mi++)
#pragma unroll
                for (int ni = 0; ni < 4; ni++)
                    mma_16816(acc[mi][ni], a4[mi], &bl[ni * 2]);   // W * Hlo
        }
    }

    // epilogue: transpose-stage, split store
    __syncthreads();
    __half* stage_hi = (__half*)smem;            // [128 l][136 c]
    __half* stage_lo = (__half*)(smem + 34816);
    const int g = lane >> 2, tg = lane & 3;
#pragma unroll
    for (int mi = 0; mi < 4; mi++) {
        const int row0 = warp_m * 64 + mi * 16 + g;
#pragma unroll
        for (int ni = 0; ni < 4; ni++) {
            const int col = warp_n * 32 + ni * 8 + tg * 2;
#pragma unroll
            for (int e = 0; e < 4; e++) {
                const int row = row0 + ((e >> 1) << 3);        // c-local
                const int c   = col + (e & 1);                 // l-local
                __half h, l;
                split_f16(acc[mi][ni][e], h, l);
                stage_hi[c * 136 + row] = h;
                stage_lo[c * 136 + row] = l;
            }
        }
    }
    __syncthreads();
    {
        const int row  = tid >> 1;                              // l-local
        const int half = tid & 1;
        const char* sh = (const char*)stage_hi + row * 272 + half * 128;
        const char* sl = (const char*)stage_lo + row * 272 + half * 128;
        const size_t grow = (size_t)rtile * 128 + row;          // global l row
        __half* oh = out_hi + grow * HID + otile * 128 + half * 64;
        __half* ol = out_lo + grow * HID + otile * 128 + half * 64;
#pragma unroll
        for (int k = 0; k < 8; k++) {
            ((uint4*)oh)[k] = ((const uint4*)sh)[k];
            ((uint4*)ol)[k] = ((const uint4*)sl)[k];
        }
    }
}

// ---------------------------------------------------------------------------
// Dilated conv layer via mma.sync fp16 2-pass (W fp16, H split hi/lo).
// 6 phases (tap outer, i-chunk of 128 inner), single-buffered -> 2 CTA/SM.
// ---------------------------------------------------------------------------
__global__ __launch_bounds__(256, 2) void conv_mma_kernel(
    const __half* __restrict__ in_hi, const __half* __restrict__ in_lo,
    const __half* __restrict__ w16, const float* __restrict__ bias,
    __half* __restrict__ out_hi, __half* __restrict__ out_lo, int d)
{
    extern __shared__ char smem[];
    const uint32_t sb = smem_u32(smem);
    const uint32_t sbA = sb, sbBh = sb + ABUF, sbBl = sb + 2 * ABUF;
    const int tid = threadIdx.x;
    const int wid = tid >> 5, lane = tid & 31;
    const int warp_m = wid >> 2, warp_n = wid & 3;
    const int ltile = blockIdx.x, otile = blockIdx.y, n = blockIdx.z;

    const __half* Hh = in_hi + (size_t)n * HLC;
    const __half* Hl = in_lo + (size_t)n * HLC;

    float acc[4][4][4];
#pragma unroll
    for (int mi = 0; mi < 4; mi++)
#pragma unroll
        for (int ni = 0; ni < 4; ni++)
#pragma unroll
            for (int e = 0; e < 4; e++) acc[mi][ni][e] = 0.f;

    const int aRow = warp_m * 64 + (lane & 15);
    const int aCol = (lane >> 4) << 3;
    const int bRow = warp_n * 32 + ((lane & 7) | ((lane >> 4) << 3));
    const int bCol = ((lane >> 3) & 1) << 3;

#pragma unroll 1
    for (int t = 0; t < 3; t++) {
        const int shift = (t - 1) * d;
#pragma unroll 1
        for (int i0 = 0; i0 < HID; i0 += 128) {
            __syncthreads();                   // prior phase's ldsm done
            // A: weight slice [128 o][128 i]
            for (int idx = tid; idx < 2048; idx += 256) {
                const int r = idx >> 4, ch = idx & 15;
                const size_t gsrc = (size_t)t * WPLANE
                                  + (size_t)(otile * 128 + r) * HID + i0 + ch * 8;
                const uint32_t sdst = (uint32_t)(r * LDA + ch * 8) * 2;
                cp16(sbA + sdst, w16 + gsrc, 16);
            }
            // B: shifted activation slice [128 l][128 i] hi/lo, zero-padded
            for (int idx = tid; idx < 2048; idx += 256) {
                const int r = idx >> 4, ch = idx & 15;
                const int lsrc = ltile * 128 + r + shift;
                const bool ok = (lsrc >= 0) && (lsrc < CHLEN);
                const size_t goff = (size_t)(ok ? lsrc : 0) * HID + i0 + ch * 8;
                const int ssz = ok ? 16 : 0;
                const uint32_t sdst = (uint32_t)(r * LDA + ch * 8) * 2;
                cp16(sbBh + sdst, Hh + goff, ssz);
                cp16(sbBl + sdst, Hl + goff, ssz);
            }
            cp_commit_wait();
            __syncthreads();
#pragma unroll
            for (int ks = 0; ks < 8; ks++) {
                uint32_t a4[4][4], bh[8], bl[8];
#pragma unroll
                for (int mi = 0; mi < 4; mi++) {
                    const uint32_t off = (uint32_t)(((aRow + mi * 16) * LDA) + aCol + ks * 16) * 2;
                    ldsm_x4(a4[mi], sbA + off);
                }
#pragma unroll
                for (int bi = 0; bi < 2; bi++) {
                    const uint32_t off = (uint32_t)(((bRow + bi * 16) * LDA) + bCol + ks * 16) * 2;
                    ldsm_x4(&bh[bi * 4], sbBh + off);
                    ldsm_x4(&bl[bi * 4], sbBl + off);
                }
#pragma unroll
                for (int mi = 0; mi < 4; mi++)
#pragma unroll
                    for (int ni = 0; ni < 4; ni++)
                        mma_16816(acc[mi][ni], a4[mi], &bh[ni * 2]);   // W * Hhi
#pragma unroll
                for (int mi = 0; mi < 4; mi++)
#pragma unroll
                    for (int ni = 0; ni < 4; ni++)
                        mma_16816(acc[mi][ni], a4[mi], &bl[ni * 2]);   // W * Hlo
            }
        }
    }

    // ---- epilogue: bias + exact gelu + residual, stage [l][o], split store
    __syncthreads();
    __half* stage_hi = (__half*)smem;            // [128 l][136 o]
    __half* stage_lo = (__half*)(smem + 34816);
    const int g = lane >> 2, tg = lane & 3;
#pragma unroll
    for (int mi = 0; mi < 4; mi++) {
        const int row0 = warp_m * 64 + mi * 16 + g;
        const float b0 = bias[otile * 128 + row0];
        const float b8 = bias[otile * 128 + row0 + 8];
#pragma unroll
        for (int ni = 0; ni < 4; ni++) {
            const int col = warp_n * 32 + ni * 8 + tg * 2;
#pragma unroll
            for (int e = 0; e < 4; e++) {
                const int row = row0 + ((e >> 1) << 3);
                const int c   = col + (e & 1);
                float v = acc[mi][ni][e] + ((e < 2) ? b0 : b8);
                float r = fmaf(v, normcdff(v), v);             // gelu(v) + v
                __half h, l;
                split_f16(r, h, l);
                stage_hi[c * 136 + row] = h;
                stage_lo[c * 136 + row] = l;
            }
        }
    }
    __syncthreads();
    {
        const int row  = tid >> 1;                              // l-local
        const int half = tid & 1;                               // o 64-half
        const char* sh = (const char*)stage_hi + row * 272 + half * 128;
        const char* sl = (const char*)stage_lo + row * 272 + half * 128;
        __half* oh = out_hi + (size_t)n * HLC +
                     (size_t)(ltile * 128 + row) * HID + otile * 128 + half * 64;
        __half* ol = out_lo + (size_t)n * HLC +
                     (size_t)(ltile * 128 + row) * HID + otile * 128 + half * 64;
#pragma unroll
        for (int k = 0; k < 8; k++) {
            ((uint4*)oh)[k] = ((const uint4*)sh)[k];
            ((uint4*)ol)[k] = ((const uint4*)sl)[k];
        }
    }
}

// ---------------------------------------------------------------------------
// Profile head, [l][c] layout: out[l] = b + sum_k sum_c w[c][k] h[l+k-9][c]
// ---------------------------------------------------------------------------
#define PROF_Q_ROWS 531
#define PROF_SMEM   (PROF_Q_ROWS * 20 * 4 + 16 + HID * 20 * 4)

__global__ __launch_bounds__(256) void profile_head_kernel(
    const __half* __restrict__ in_hi, const __half* __restrict__ in_lo,
    const float* __restrict__ wprof, const float* __restrict__ bprof,
    float* __restrict__ out)
{
    extern __shared__ char smem[];
    float* Qs  = (float*)smem;                         // [531][20]
    float* wsh = (float*)(smem + PROF_Q_ROWS * 20 * 4 + 16);
    const int n = blockIdx.x, tid = threadIdx.x;
    const int wid = tid >> 5, lane = tid & 31;

    for (int i = tid; i < HID * 20; i += 256) wsh[i] = wprof[i];
    for (int i = tid; i < PROF_Q_ROWS * 20; i += 256) Qs[i] = 0.f;
    __syncthreads();

    const __half* Hh = in_hi + (size_t)n * HLC;
    const __half* Hl = in_lo + (size_t)n * HLC;
    for (int row = wid; row < CHLEN; row += 8) {
        uint4 uh = *(const uint4*)(Hh + (size_t)row * HID + lane * 8);
        uint4 ul = *(const uint4*)(Hl + (size_t)row * HID + lane * 8);
        const __half* ph = (const __half*)&uh;
        const __half* pl = (const __half*)&ul;
        float acc[20];
#pragma unroll
        for (int k = 0; k < 20; k++) acc[k] = 0.f;
#pragma unroll
        for (int cc = 0; cc < 8; cc++) {
            float hv = __half2float(ph[cc]) + __half2float(pl[cc]);
            const float* wr = &wsh[(lane * 8 + cc) * 20];
#pragma unroll
            for (int k = 0; k < 20; k++) acc[k] = fmaf(hv, wr[k], acc[k]);
        }
#pragma unroll
        for (int off = 16; off > 0; off >>= 1)
#pragma unroll
            for (int k = 0; k < 20; k++)
                acc[k] += __shfl_xor_sync(0xFFFFFFFF, acc[k], off);
        if (lane < 20) Qs[(row + 9) * 20 + lane] = acc[lane];
    }
    __syncthreads();

    const float bz = bprof[0];
    for (int l = tid; l < CHLEN; l += 256) {
        float s = bz;
#pragma unroll
        for (int k = 0; k < 20; k++) s += Qs[(l + k) * 20 + k];
        out[NCHUNK + (size_t)n * CHLEN + l] = s;
    }
}

// ---------------------------------------------------------------------------
// atpm head, [l][c] layout; n_peaks is int32 (JAX x64-disabled)
// ---------------------------------------------------------------------------
__global__ __launch_bounds__(256) void atpm_head_kernel(
    const __half* __restrict__ in_hi, const __half* __restrict__ in_lo,
    const float* __restrict__ watpm, const float* __restrict__ batpm,
    const int* __restrict__ npeaks, float* __restrict__ out)
{
    __shared__ float red[256];
    const int n = blockIdx.x, tid = threadIdx.x;
    const __half* Hh = in_hi + (size_t)n * HLC + tid;
    const __half* Hl = in_lo + (size_t)n * HLC + tid;
    float s = 0.f;
    for (int l = 0; l < CHLEN; l++)
        s += __half2float(Hh[(size_t)l * HID]) + __half2float(Hl[(size_t)l * HID]);
    red[tid] = s * watpm[tid];
    __syncthreads();
    for (int off = 128; off > 0; off >>= 1) {
        if (tid < off) red[tid] += red[tid + off];
        __syncthreads();
    }
    if (tid == 0) {
        float v = red[0] * (1.f / (float)CHLEN) + batpm[0];
        int b = n >> 7, p = n & 127;
        out[n] = (p < npeaks[b]) ? v : 0.f;
    }
}

// ---------------------------------------------------------------------------
extern "C" void kernel_launch(void* const* d_in, const int* in_sizes, int n_in,
                              void* d_out, int out_size)
{
    const float* x       = (const float*)d_in[0];
    const float* w_proj  = (const float*)d_in[1];
    const float* tower_w = (const float*)d_in[2];
    const float* tower_b = (const float*)d_in[3];
    const float* w_prof  = (const float*)d_in[4];
    const float* b_prof  = (const float*)d_in[5];
    const float* w_atpm  = (const float*)d_in[6];
    const float* b_atpm  = (const float*)d_in[7];
    const int*   n_peaks = (const int*)d_in[8];
    float* out = (float*)d_out;

    __half *hiA, *loA, *hiB, *loB, *w16, *xHi, *xLo, *wp16;
    cudaGetSymbolAddress((void**)&hiA, g_hiA);
    cudaGetSymbolAddress((void**)&loA, g_loA);
    cudaGetSymbolAddress((void**)&hiB, g_hiB);
    cudaGetSymbolAddress((void**)&loB, g_loB);
    cudaGetSymbolAddress((void**)&w16, g_w16);
    cudaGetSymbolAddress((void**)&xHi, g_xHi);
    cudaGetSymbolAddress((void**)&xLo, g_xLo);
    cudaGetSymbolAddress((void**)&wp16, g_wp16);

    cudaFuncSetAttribute(conv_mma_kernel,
                         cudaFuncAttributeMaxDynamicSharedMemorySize, SM_MMA);
    cudaFuncSetAttribute(proj_mma_kernel,
                         cudaFuncAttributeMaxDynamicSharedMemorySize, SM_MMA);
    cudaFuncSetAttribute(profile_head_kernel,
                         cudaFuncAttributeMaxDynamicSharedMemorySize, PROF_SMEM);

    wprep_kernel<<<DEPTH * 3 * WPLANE / 256, 256>>>(tower_w, w16);
    wpsplit_kernel<<<HID, 256>>>(w_proj, wp16);
    xsplit_kernel<<<NROWS, 256>>>(x, xHi, xLo);
    proj_mma_kernel<<<dim3(NROWS / 128, 2), 256, SM_MMA>>>(xHi, xLo, wp16, hiA, loA);

    __half *ch = hiA, *cl = loA, *nh = hiB, *nl = loB;
    for (int i = 0; i < DEPTH; i++) {
        int d = 2 << i;          // 2^(i+1)
        conv_mma_kernel<<<dim3(4, 2, NCHUNK), 256, SM_MMA>>>(
            ch, cl, w16 + (size_t)i * 3 * WPLANE,
            tower_b + i * HID, nh, nl, d);
        __half* t;
        t = ch; ch = nh; nh = t;
        t = cl; cl = nl; nl = t;
    }

    profile_head_kernel<<<NCHUNK, 256, PROF_SMEM>>>(ch, cl, w_prof, b_prof, out);
    atpm_head_kernel<<<NCHUNK, 256>>>(ch, cl, w_atpm, b_atpm, n_peaks, out);
}

// round 16
// speedup vs baseline: 1.0355x; 1.0355x over previous
#include <cuda_runtime.h>
#include <cuda_fp16.h>
#include <cstdint>

// Problem constants
#define NCHUNK  256            // BATCH * NPEAK
#define CHLEN   512
#define HID     256
#define MDIM    283
#define KPADP   320            // proj K padded to 5*64
#define DEPTH   7
#define HLC     131072         // CHLEN * HID elements per chunk, [l][c] layout
#define NROWS   131072         // total l rows (NCHUNK * CHLEN)
#define BUF_ELEMS ((size_t)NCHUNK * HLC)

// Activation ping-pong buffers, split fp16 (hi + lo reconstructs fp32 to ~2^-22)
__device__ __half g_hiA[BUF_ELEMS];
__device__ __half g_loA[BUF_ELEMS];
__device__ __half g_hiB[BUF_ELEMS];
__device__ __half g_loB[BUF_ELEMS];

// Tower weights as single fp16 (11-bit mantissa): [layer][tap][o][i]
#define WPLANE 65536                               // 256*256 per (layer,tap)
__device__ __half g_w16[DEPTH * 3 * WPLANE];

// x split fp16 hi/lo + w_proj single fp16, K padded to 320
__device__ __half g_xHi[(size_t)NROWS * KPADP];
__device__ __half g_xLo[(size_t)NROWS * KPADP];
__device__ __half g_wp16[HID * KPADP];

__device__ __forceinline__ uint32_t smem_u32(const void* p) {
    uint32_t a;
    asm("{ .reg .u64 t; cvta.to.shared.u64 t, %1; cvt.u32.u64 %0, t; }" : "=r"(a) : "l"(p));
    return a;
}
__device__ __forceinline__ void split_f16(float v, __half& h, __half& l) {
    h = __float2half_rn(v);
    l = __float2half_rn(v - __half2float(h));
}
__device__ __forceinline__ void ldsm_x4(uint32_t* r, uint32_t addr) {
    asm volatile("ldmatrix.sync.aligned.m8n8.x4.shared.b16 {%0,%1,%2,%3}, [%4];"
        : "=r"(r[0]), "=r"(r[1]), "=r"(r[2]), "=r"(r[3]) : "r"(addr));
}
__device__ __forceinline__ void mma_16816(float* d, const uint32_t* a, const uint32_t* b) {
    asm volatile("mma.sync.aligned.m16n8k16.row.col.f32.f16.f16.f32 "
        "{%0,%1,%2,%3},{%4,%5,%6,%7},{%8,%9},{%0,%1,%2,%3};"
        : "+f"(d[0]), "+f"(d[1]), "+f"(d[2]), "+f"(d[3])
        : "r"(a[0]), "r"(a[1]), "r"(a[2]), "r"(a[3]), "r"(b[0]), "r"(b[1]));
}
__device__ __forceinline__ void cp16(uint32_t dst, const void* src, int srcsize) {
    asm volatile("cp.async.cg.shared.global [%0], [%1], 16, %2;"
                 :: "r"(dst), "l"(src), "r"(srcsize) : "memory");
}
__device__ __forceinline__ void cp_commit() {
    asm volatile("cp.async.commit_group;" ::: "memory");
}
__device__ __forceinline__ void cp_wait1() {
    asm volatile("cp.async.wait_group 1;" ::: "memory");
}
__device__ __forceinline__ void cp_wait0() {
    asm volatile("cp.async.wait_group 0;" ::: "memory");
}

// ---------------------------------------------------------------------------
// Prep kernels
// ---------------------------------------------------------------------------
__global__ __launch_bounds__(256) void wprep_kernel(
    const float* __restrict__ w, __half* __restrict__ w16)
{
    size_t j = (size_t)blockIdx.x * 256 + threadIdx.x;     // < DEPTH*3*WPLANE
    int layer = (int)(j / (3 * WPLANE));
    int rem   = (int)(j % (3 * WPLANE));
    int t  = rem / WPLANE;
    int oi = rem % WPLANE;                                  // o*256 + i
    float v = w[(size_t)layer * 3 * WPLANE + (size_t)oi * 3 + t];
    w16[j] = __float2half_rn(v);
}

__global__ __launch_bounds__(256) void xsplit_kernel(
    const float* __restrict__ x, __half* __restrict__ xh, __half* __restrict__ xl)
{
    const size_t row = blockIdx.x;                          // < NROWS
    for (int m = threadIdx.x; m < KPADP; m += 256) {
        float v = (m < MDIM) ? x[row * MDIM + m] : 0.f;
        __half h, l;
        split_f16(v, h, l);
        xh[row * KPADP + m] = h;
        xl[row * KPADP + m] = l;
    }
}

__global__ __launch_bounds__(256) void wpsplit_kernel(
    const float* __restrict__ wp, __half* __restrict__ w16)
{
    const size_t c = blockIdx.x;                            // < HID
    for (int m = threadIdx.x; m < KPADP; m += 256) {
        float v = (m < MDIM) ? wp[c * MDIM + m] : 0.f;
        w16[c * KPADP + m] = __float2half_rn(v);
    }
}

// ---------------------------------------------------------------------------
// MMA tile geometry: fp16 2-pass, K=64 phases, 2-stage cp.async pipeline.
// CTA: 128 M x 128 N; 8 warps (2x4), warp tile 64x32.
// Stage: A(single) + B hi/lo, each 128 x 64 fp16 with LDA=72 pad.
// Stage = 3*18432 = 55296 B; 2 stages = 110592 B -> 2 CTAs/SM (216K < 228K).
// ---------------------------------------------------------------------------
#define LDA     72
#define ABUF    18432
#define STG     55296
#define SM_MMA  110592

// ---------------------------------------------------------------------------
// Projection via mma: D[c, row] = sum_m wp[c,m] x[row,m]; K=320, 5 phases.
// ---------------------------------------------------------------------------
__global__ __launch_bounds__(256, 2) void proj_mma_kernel(
    const __half* __restrict__ xh, const __half* __restrict__ xl,
    const __half* __restrict__ w16,
    __half* __restrict__ out_hi, __half* __restrict__ out_lo)
{
    extern __shared__ char smem[];
    const uint32_t sb = smem_u32(smem);
    const int tid = threadIdx.x;
    const int wid = tid >> 5, lane = tid & 31;
    const int warp_m = wid >> 2, warp_n = wid & 3;
    const int rtile = blockIdx.x;        // row tile (128 rows)
    const int otile = blockIdx.y;        // c half

    float acc[4][4][4];
#pragma unroll
    for (int mi = 0; mi < 4; mi++)
#pragma unroll
        for (int ni = 0; ni < 4; ni++)
#pragma unroll
            for (int e = 0; e < 4; e++) acc[mi][ni][e] = 0.f;

    const int aRow = warp_m * 64 + (lane & 15);
    const int aCol = (lane >> 4) << 3;
    const int bRow = warp_n * 32 + ((lane & 7) | ((lane >> 4) << 3));
    const int bCol = ((lane >> 3) & 1) << 3;

    auto fill = [&](int p, int s) {
        const int k0 = p * 64;
        const uint32_t st = sb + (uint32_t)s * STG;
        for (int idx = tid; idx < 1024; idx += 256) {
            const int r = idx >> 3, ch = idx & 7;
            const size_t gsrc = (size_t)(otile * 128 + r) * KPADP + k0 + ch * 8;
            const uint32_t sdst = (uint32_t)(r * LDA + ch * 8) * 2;
            cp16(st + sdst, w16 + gsrc, 16);
        }
        for (int idx = tid; idx < 1024; idx += 256) {
            const int r = idx >> 3, ch = idx & 7;
            const size_t gsrc = ((size_t)rtile * 128 + r) * KPADP + k0 + ch * 8;
            const uint32_t sdst = (uint32_t)(r * LDA + ch * 8) * 2;
            cp16(st + ABUF + sdst, xh + gsrc, 16);
            cp16(st + 2 * ABUF + sdst, xl + gsrc, 16);
        }
        cp_commit();
    };

    fill(0, 0);
#pragma unroll 1
    for (int p = 0; p < 5; p++) {
        const int s = p & 1;
        if (p + 1 < 5) { fill(p + 1, s ^ 1); cp_wait1(); }
        else           { cp_wait0(); }
        __syncthreads();
        const uint32_t st = sb + (uint32_t)s * STG;
#pragma unroll
        for (int ks = 0; ks < 4; ks++) {
            uint32_t a4[4][4], bh[8], bl[8];
#pragma unroll
            for (int mi = 0; mi < 4; mi++) {
                const uint32_t off = (uint32_t)(((aRow + mi * 16) * LDA) + aCol + ks * 16) * 2;
                ldsm_x4(a4[mi], st + off);
            }
#pragma unroll
            for (int bi = 0; bi < 2; bi++) {
                const uint32_t off = (uint32_t)(((bRow + bi * 16) * LDA) + bCol + ks * 16) * 2;
                ldsm_x4(&bh[bi * 4], st + ABUF + off);
                ldsm_x4(&bl[bi * 4], st + 2 * ABUF + off);
            }
#pragma unroll
            for (int mi = 0; mi < 4; mi++)
#pragma unroll
                for (int ni = 0; ni < 4; ni++)
                    mma_16816(acc[mi][ni], a4[mi], &bh[ni * 2]);   // W * Hhi
#pragma unroll
            for (int mi = 0; mi < 4; mi++)
#pragma unroll
                for (int ni = 0; ni < 4; ni++)
                    mma_16816(acc[mi][ni], a4[mi], &bl[ni * 2]);   // W * Hlo
        }
        __syncthreads();
    }

    // epilogue: transpose-stage, split store
    __half* stage_hi = (__half*)smem;            // [128 l][136 c]
    __half* stage_lo = (__half*)(smem + 36864);
    const int g = lane >> 2, tg = lane & 3;
#pragma unroll
    for (int mi = 0; mi < 4; mi++) {
        const int row0 = warp_m * 64 + mi * 16 + g;
#pragma unroll
        for (int ni = 0; ni < 4; ni++) {
            const int col = warp_n * 32 + ni * 8 + tg * 2;
#pragma unroll
            for (int e = 0; e < 4; e++) {
                const int row = row0 + ((e >> 1) << 3);        // c-local
                const int c   = col + (e & 1);                 // l-local
                __half h, l;
                split_f16(acc[mi][ni][e], h, l);
                stage_hi[c * 136 + row] = h;
                stage_lo[c * 136 + row] = l;
            }
        }
    }
    __syncthreads();
    {
        const int row  = tid >> 1;                              // l-local
        const int half = tid & 1;
        const char* sh = (const char*)stage_hi + row * 272 + half * 128;
        const char* sl = (const char*)stage_lo + row * 272 + half * 128;
        const size_t grow = (size_t)rtile * 128 + row;          // global l row
        __half* oh = out_hi + grow * HID + otile * 128 + half * 64;
        __half* ol = out_lo + grow * HID + otile * 128 + half * 64;
#pragma unroll
        for (int k = 0; k < 8; k++) {
            ((uint4*)oh)[k] = ((const uint4*)sh)[k];
            ((uint4*)ol)[k] = ((const uint4*)sl)[k];
        }
    }
}

// ---------------------------------------------------------------------------
// Dilated conv layer via mma.sync fp16 2-pass (W fp16, H split hi/lo).
// 12 phases (tap t = p/4, i0 = (p%4)*64), 2-stage pipelined -> 2 CTA/SM.
// ---------------------------------------------------------------------------
__global__ __launch_bounds__(256, 2) void conv_mma_kernel(
    const __half* __restrict__ in_hi, const __half* __restrict__ in_lo,
    const __half* __restrict__ w16, const float* __restrict__ bias,
    __half* __restrict__ out_hi, __half* __restrict__ out_lo, int d)
{
    extern __shared__ char smem[];
    const uint32_t sb = smem_u32(smem);
    const int tid = threadIdx.x;
    const int wid = tid >> 5, lane = tid & 31;
    const int warp_m = wid >> 2, warp_n = wid & 3;
    const int ltile = blockIdx.x, otile = blockIdx.y, n = blockIdx.z;

    const __half* Hh = in_hi + (size_t)n * HLC;
    const __half* Hl = in_lo + (size_t)n * HLC;

    float acc[4][4][4];
#pragma unroll
    for (int mi = 0; mi < 4; mi++)
#pragma unroll
        for (int ni = 0; ni < 4; ni++)
#pragma unroll
            for (int e = 0; e < 4; e++) acc[mi][ni][e] = 0.f;

    const int aRow = warp_m * 64 + (lane & 15);
    const int aCol = (lane >> 4) << 3;
    const int bRow = warp_n * 32 + ((lane & 7) | ((lane >> 4) << 3));
    const int bCol = ((lane >> 3) & 1) << 3;

    auto fill = [&](int p, int s) {
        const int t  = p >> 2;
        const int i0 = (p & 3) * 64;
        const int shift = (t - 1) * d;
        const uint32_t st = sb + (uint32_t)s * STG;
        // A: weight slice [128 o][64 i]
        for (int idx = tid; idx < 1024; idx += 256) {
            const int r = idx >> 3, ch = idx & 7;
            const size_t gsrc = (size_t)t * WPLANE
                              + (size_t)(otile * 128 + r) * HID + i0 + ch * 8;
            const uint32_t sdst = (uint32_t)(r * LDA + ch * 8) * 2;
            cp16(st + sdst, w16 + gsrc, 16);
        }
        // B: shifted activation slice [128 l][64 i] hi/lo, zero-padded
        for (int idx = tid; idx < 1024; idx += 256) {
            const int r = idx >> 3, ch = idx & 7;
            const int lsrc = ltile * 128 + r + shift;
            const bool ok = (lsrc >= 0) && (lsrc < CHLEN);
            const size_t goff = (size_t)(ok ? lsrc : 0) * HID + i0 + ch * 8;
            const int ssz = ok ? 16 : 0;
            const uint32_t sdst = (uint32_t)(r * LDA + ch * 8) * 2;
            cp16(st + ABUF + sdst, Hh + goff, ssz);
            cp16(st + 2 * ABUF + sdst, Hl + goff, ssz);
        }
        cp_commit();
    };

    fill(0, 0);
#pragma unroll 1
    for (int p = 0; p < 12; p++) {
        const int s = p & 1;
        if (p + 1 < 12) { fill(p + 1, s ^ 1); cp_wait1(); }
        else            { cp_wait0(); }
        __syncthreads();
        const uint32_t st = sb + (uint32_t)s * STG;
#pragma unroll
        for (int ks = 0; ks < 4; ks++) {
            uint32_t a4[4][4], bh[8], bl[8];
#pragma unroll
            for (int mi = 0; mi < 4; mi++) {
                const uint32_t off = (uint32_t)(((aRow + mi * 16) * LDA) + aCol + ks * 16) * 2;
                ldsm_x4(a4[mi], st + off);
            }
#pragma unroll
            for (int bi = 0; bi < 2; bi++) {
                const uint32_t off = (uint32_t)(((bRow + bi * 16) * LDA) + bCol + ks * 16) * 2;
                ldsm_x4(&bh[bi * 4], st + ABUF + off);
                ldsm_x4(&bl[bi * 4], st + 2 * ABUF + off);
            }
#pragma unroll
            for (int mi = 0; mi < 4; mi++)
#pragma unroll
                for (int ni = 0; ni < 4; ni++)
                    mma_16816(acc[mi][ni], a4[mi], &bh[ni * 2]);   // W * Hhi
#pragma unroll
            for (int mi = 0; mi < 4; mi++)
#pragma unroll
                for (int ni = 0; ni < 4; ni++)
                    mma_16816(acc[mi][ni], a4[mi], &bl[ni * 2]);   // W * Hlo
        }
        __syncthreads();
    }

    // ---- epilogue: bias + exact gelu + residual, stage [l][o], split store
    __half* stage_hi = (__half*)smem;            // [128 l][136 o]
    __half* stage_lo = (__half*)(smem + 36864);
    const int g = lane >> 2, tg = lane & 3;
#pragma unroll
    for (int mi = 0; mi < 4; mi++) {
        const int row0 = warp_m * 64 + mi * 16 + g;
        const float b0 = bias[otile * 128 + row0];
        const float b8 = bias[otile * 128 + row0 + 8];
#pragma unroll
        for (int ni = 0; ni < 4; ni++) {
            const int col = warp_n * 32 + ni * 8 + tg * 2;
#pragma unroll
            for (int e = 0; e < 4; e++) {
                const int row = row0 + ((e >> 1) << 3);
                const int c   = col + (e & 1);
                float v = acc[mi][ni][e] + ((e < 2) ? b0 : b8);
                float r = fmaf(v, normcdff(v), v);             // gelu(v) + v
                __half h, l;
                split_f16(r, h, l);
                stage_hi[c * 136 + row] = h;
                stage_lo[c * 136 + row] = l;
            }
        }
    }
    __syncthreads();
    {
        const int row  = tid >> 1;                              // l-local
        const int half = tid & 1;                               // o 64-half
        const char* sh = (const char*)stage_hi + row * 272 + half * 128;
        const char* sl = (const char*)stage_lo + row * 272 + half * 128;
        __half* oh = out_hi + (size_t)n * HLC +
                     (size_t)(ltile * 128 + row) * HID + otile * 128 + half * 64;
        __half* ol = out_lo + (size_t)n * HLC +
                     (size_t)(ltile * 128 + row) * HID + otile * 128 + half * 64;
#pragma unroll
        for (int k = 0; k < 8; k++) {
            ((uint4*)oh)[k] = ((const uint4*)sh)[k];
            ((uint4*)ol)[k] = ((const uint4*)sl)[k];
        }
    }
}

// ---------------------------------------------------------------------------
// Profile head, [l][c] layout: out[l] = b + sum_k sum_c w[c][k] h[l+k-9][c]
// ---------------------------------------------------------------------------
#define PROF_Q_ROWS 531
#define PROF_SMEM   (PROF_Q_ROWS * 20 * 4 + 16 + HID * 20 * 4)

__global__ __launch_bounds__(256) void profile_head_kernel(
    const __half* __restrict__ in_hi, const __half* __restrict__ in_lo,
    const float* __restrict__ wprof, const float* __restrict__ bprof,
    float* __restrict__ out)
{
    extern __shared__ char smem[];
    float* Qs  = (float*)smem;                         // [531][20]
    float* wsh = (float*)(smem + PROF_Q_ROWS * 20 * 4 + 16);
    const int n = blockIdx.x, tid = threadIdx.x;
    const int wid = tid >> 5, lane = tid & 31;

    for (int i = tid; i < HID * 20; i += 256) wsh[i] = wprof[i];
    for (int i = tid; i < PROF_Q_ROWS * 20; i += 256) Qs[i] = 0.f;
    __syncthreads();

    const __half* Hh = in_hi + (size_t)n * HLC;
    const __half* Hl = in_lo + (size_t)n * HLC;
    for (int row = wid; row < CHLEN; row += 8) {
        uint4 uh = *(const uint4*)(Hh + (size_t)row * HID + lane * 8);
        uint4 ul = *(const uint4*)(Hl + (size_t)row * HID + lane * 8);
        const __half* ph = (const __half*)&uh;
        const __half* pl = (const __half*)&ul;
        float acc[20];
#pragma unroll
        for (int k = 0; k < 20; k++) acc[k] = 0.f;
#pragma unroll
        for (int cc = 0; cc < 8; cc++) {
            float hv = __half2float(ph[cc]) + __half2float(pl[cc]);
            const float* wr = &wsh[(lane * 8 + cc) * 20];
#pragma unroll
            for (int k = 0; k < 20; k++) acc[k] = fmaf(hv, wr[k], acc[k]);
        }
#pragma unroll
        for (int off = 16; off > 0; off >>= 1)
#pragma unroll
            for (int k = 0; k < 20; k++)
                acc[k] += __shfl_xor_sync(0xFFFFFFFF, acc[k], off);
        if (lane < 20) Qs[(row + 9) * 20 + lane] = acc[lane];
    }
    __syncthreads();

    const float bz = bprof[0];
    for (int l = tid; l < CHLEN; l += 256) {
        float s = bz;
#pragma unroll
        for (int k = 0; k < 20; k++) s += Qs[(l + k) * 20 + k];
        out[NCHUNK + (size_t)n * CHLEN + l] = s;
    }
}

// ---------------------------------------------------------------------------
// atpm head, [l][c] layout; n_peaks is int32 (JAX x64-disabled)
// ---------------------------------------------------------------------------
__global__ __launch_bounds__(256) void atpm_head_kernel(
    const __half* __restrict__ in_hi, const __half* __restrict__ in_lo,
    const float* __restrict__ watpm, const float* __restrict__ batpm,
    const int* __restrict__ npeaks, float* __restrict__ out)
{
    __shared__ float red[256];
    const int n = blockIdx.x, tid = threadIdx.x;
    const __half* Hh = in_hi + (size_t)n * HLC + tid;
    const __half* Hl = in_lo + (size_t)n * HLC + tid;
    float s = 0.f;
    for (int l = 0; l < CHLEN; l++)
        s += __half2float(Hh[(size_t)l * HID]) + __half2float(Hl[(size_t)l * HID]);
    red[tid] = s * watpm[tid];
    __syncthreads();
    for (int off = 128; off > 0; off >>= 1) {
        if (tid < off) red[tid] += red[tid + off];
        __syncthreads();
    }
    if (tid == 0) {
        float v = red[0] * (1.f / (float)CHLEN) + batpm[0];
        int b = n >> 7, p = n & 127;
        out[n] = (p < npeaks[b]) ? v : 0.f;
    }
}

// ---------------------------------------------------------------------------
extern "C" void kernel_launch(void* const* d_in, const int* in_sizes, int n_in,
                              void* d_out, int out_size)
{
    const float* x       = (const float*)d_in[0];
    const float* w_proj  = (const float*)d_in[1];
    const float* tower_w = (const float*)d_in[2];
    const float* tower_b = (const float*)d_in[3];
    const float* w_prof  = (const float*)d_in[4];
    const float* b_prof  = (const float*)d_in[5];
    const float* w_atpm  = (const float*)d_in[6];
    const float* b_atpm  = (const float*)d_in[7];
    const int*   n_peaks = (const int*)d_in[8];
    float* out = (float*)d_out;

    __half *hiA, *loA, *hiB, *loB, *w16, *xHi, *xLo, *wp16;
    cudaGetSymbolAddress((void**)&hiA, g_hiA);
    cudaGetSymbolAddress((void**)&loA, g_loA);
    cudaGetSymbolAddress((void**)&hiB, g_hiB);
    cudaGetSymbolAddress((void**)&loB, g_loB);
    cudaGetSymbolAddress((void**)&w16, g_w16);
    cudaGetSymbolAddress((void**)&xHi, g_xHi);
    cudaGetSymbolAddress((void**)&xLo, g_xLo);
    cudaGetSymbolAddress((void**)&wp16, g_wp16);

    cudaFuncSetAttribute(conv_mma_kernel,
                         cudaFuncAttributeMaxDynamicSharedMemorySize, SM_MMA);
    cudaFuncSetAttribute(proj_mma_kernel,
                         cudaFuncAttributeMaxDynamicSharedMemorySize, SM_MMA);
    cudaFuncSetAttribute(profile_head_kernel,
                         cudaFuncAttributeMaxDynamicSharedMemorySize, PROF_SMEM);

    wprep_kernel<<<DEPTH * 3 * WPLANE / 256, 256>>>(tower_w, w16);
    wpsplit_kernel<<<HID, 256>>>(w_proj, wp16);
    xsplit_kernel<<<NROWS, 256>>>(x, xHi, xLo);
    proj_mma_kernel<<<dim3(NROWS / 128, 2), 256, SM_MMA>>>(xHi, xLo, wp16, hiA, loA);

    __half *ch = hiA, *cl = loA, *nh = hiB, *nl = loB;
    for (int i = 0; i < DEPTH; i++) {
        int d = 2 << i;          // 2^(i+1)
        conv_mma_kernel<<<dim3(4, 2, NCHUNK), 256, SM_MMA>>>(
            ch, cl, w16 + (size_t)i * 3 * WPLANE,
            tower_b + i * HID, nh, nl, d);
        __half* t;
        t = ch; ch = nh; nh = t;
        t = cl; cl = nl; nl = t;
    }

    profile_head_kernel<<<NCHUNK, 256, PROF_SMEM>>>(ch, cl, w_prof, b_prof, out);
    atpm_head_kernel<<<NCHUNK, 256>>>(ch, cl, w_atpm, b_atpm, n_peaks, out);
}